// round 1
// baseline (speedup 1.0000x reference)
#include <cuda_runtime.h>

#define NN     20000
#define NEIGH  12
#define EE     (NN*NEIGH)      // 240000
#define HD     64
#define INB    480             // 40 * 12
#define INA    2880            // 20 * 144
#define NCRYS  20

// ---------------- scratch (device globals; no allocation allowed) ----------
__device__ float g_X[(size_t)NN * INA];   // expansion buffer (reused for bond/angle)
__device__ float g_H[(size_t)NN * 256];   // GEMM output: [root | rel0 | rel1 | rel2]
__device__ float g_acc[NN * HD];          // aggregation accumulator
__device__ float g_bf[NN * HD];
__device__ float g_af[NN * HD];
__device__ int   g_cnt[NN * 3];           // per-node per-relation in-degree
__device__ float g_pool[NCRYS * 128];     // crystal feature sums

// ---------------- small utility kernels ------------------------------------
__global__ void zero_kernel() {
    int i = blockIdx.x * blockDim.x + threadIdx.x;
    if (i < NN * 3) g_cnt[i] = 0;
    if (i < NCRYS * 128) g_pool[i] = 0.f;
}

__global__ void count_kernel(const int* __restrict__ nbr,
                             const int* __restrict__ species) {
    int e = blockIdx.x * blockDim.x + threadIdx.x;
    if (e >= EE) return;
    int src = e / NEIGH;
    int dst = nbr[e];
    int et  = species[src] + species[dst];
    atomicAdd(&g_cnt[dst * 3 + et], 1);
}

// gbf(bond, 0, 8, 40): gamma = 0.2, filters = i * 8/39
__global__ void expand_bond(const float* __restrict__ bond) {
    int idx = blockIdx.x * blockDim.x + threadIdx.x;
    if (idx >= NN * INB) return;
    int v = idx / INB, p = idx % INB;
    int j = p / 40,    s = p % 40;
    float d = bond[v * NEIGH + j];
    float f = (float)s * (8.0f / 39.0f);
    float t = d - f;
    g_X[(size_t)v * INB + p] = __expf(-t * t * 25.0f);   // 1/gamma^2 = 25
}

// gbf(angle, -1, 1, 20): gamma = 0.1, filters = -1 + i * 2/19
__global__ void expand_angle(const float* __restrict__ ang) {
    int idx = blockIdx.x * blockDim.x + threadIdx.x;
    if (idx >= NN * INA) return;
    int v  = idx / INA, p = idx % INA;
    int jk = p / 20,    s = p % 20;
    float d = ang[(size_t)v * 144 + jk];
    float f = -1.0f + (float)s * (2.0f / 19.0f);
    float t = d - f;
    g_X[(size_t)idx] = __expf(-t * t * 100.0f);          // 1/gamma^2 = 100
}

// ---------------- SGEMM: g_H[M,256] = X[M,K] @ [Wroot | Wrel0..2] ----------
// Block tile 128x64, BK=16, 256 threads, 8x4 per-thread microtile.
// blockIdx.y selects which of the 4 weight matrices (0=root, 1..3=rel).
__global__ void gemm_kernel(const float* __restrict__ X, int K,
                            const float* __restrict__ Wroot,
                            const float* __restrict__ Wrel) {
    __shared__ __align__(16) float As[16][132];   // transposed A tile, padded
    __shared__ __align__(16) float Bs[16][64];

    int tid  = threadIdx.x;
    int row0 = blockIdx.x * 128;
    int cb   = blockIdx.y;                        // 0..3
    const float* Wb = (cb == 0) ? Wroot : (Wrel + (size_t)(cb - 1) * K * 64);

    int tx   = tid & 15;        // column group (4 cols each)
    int ty   = tid >> 4;        // row group (8 rows each)
    int arow = tid >> 2;        // A-load row (0..63), + 64 for second half
    int akc  = (tid & 3) << 2;  // A-load k offset (0,4,8,12)
    int brow = tid >> 4;        // B-load k row (0..15)
    int bcol = (tid & 15) << 2; // B-load col (0,4,...,60)

    float acc[8][4];
#pragma unroll
    for (int i = 0; i < 8; i++)
#pragma unroll
        for (int j = 0; j < 4; j++) acc[i][j] = 0.f;

    for (int k0 = 0; k0 < K; k0 += 16) {
#pragma unroll
        for (int half = 0; half < 2; half++) {
            int r  = arow + half * 64;
            int gr = row0 + r;
            float4 va = make_float4(0.f, 0.f, 0.f, 0.f);
            if (gr < NN)
                va = *(const float4*)(X + (size_t)gr * K + (k0 + akc));
            As[akc + 0][r] = va.x;
            As[akc + 1][r] = va.y;
            As[akc + 2][r] = va.z;
            As[akc + 3][r] = va.w;
        }
        *(float4*)&Bs[brow][bcol] =
            *(const float4*)(Wb + (size_t)(k0 + brow) * 64 + bcol);
        __syncthreads();

#pragma unroll
        for (int kk = 0; kk < 16; kk++) {
            float4 a0 = *(const float4*)&As[kk][ty * 8];
            float4 a1 = *(const float4*)&As[kk][ty * 8 + 4];
            float4 bb = *(const float4*)&Bs[kk][tx * 4];
            float av[8] = {a0.x, a0.y, a0.z, a0.w, a1.x, a1.y, a1.z, a1.w};
            float bv[4] = {bb.x, bb.y, bb.z, bb.w};
#pragma unroll
            for (int i = 0; i < 8; i++)
#pragma unroll
                for (int j = 0; j < 4; j++)
                    acc[i][j] += av[i] * bv[j];
        }
        __syncthreads();
    }

#pragma unroll
    for (int i = 0; i < 8; i++) {
        int gr = row0 + ty * 8 + i;
        if (gr < NN) {
            *(float4*)(g_H + (size_t)gr * 256 + cb * 64 + tx * 4) =
                make_float4(acc[i][0], acc[i][1], acc[i][2], acc[i][3]);
        }
    }
}

// ---------------- aggregation ----------------------------------------------
__global__ void init_acc(const float* __restrict__ b) {
    int i = blockIdx.x * blockDim.x + threadIdx.x;
    if (i >= NN * HD) return;
    int h = i & 63;
    g_acc[i] = g_H[(size_t)(i >> 6) * 256 + h] + b[h];
}

__global__ void scatter_kernel(const int* __restrict__ nbr,
                               const int* __restrict__ species) {
    int idx = blockIdx.x * blockDim.x + threadIdx.x;
    if (idx >= EE * 64) return;
    int e = idx >> 6, h = idx & 63;
    int src = e / NEIGH;
    int dst = nbr[e];
    int et  = species[src] + species[dst];
    int c   = g_cnt[dst * 3 + et];
    if (c < 1) c = 1;
    float v = g_H[(size_t)src * 256 + (et + 1) * 64 + h] * (1.0f / (float)c);
    atomicAdd(&g_acc[dst * 64 + h], v);
}

__global__ void relu_copy(float* __restrict__ dstbuf) {
    int i = blockIdx.x * blockDim.x + threadIdx.x;
    if (i >= NN * HD) return;
    float v = g_acc[i];
    dstbuf[i] = v > 0.f ? v : 0.f;
}

// ---------------- pooling + final FC ----------------------------------------
#define POOL_NODES 160
__global__ void pool_kernel(const int* __restrict__ crys) {
    __shared__ int starts[NCRYS];
    int t = threadIdx.x;              // 0..127 (feature index)
    if (t < NCRYS) starts[t] = crys[t * 2];
    __syncthreads();
    int v0 = blockIdx.x * POOL_NODES;
    int v1 = v0 + POOL_NODES;
    if (v1 > NN) v1 = NN;
    const float* srcbuf = (t < 64) ? g_bf : g_af;
    int h = t & 63;
    float sum = 0.f;
    int cur = -2;
    for (int v = v0; v < v1; v++) {
        int c = 0;
#pragma unroll
        for (int k = 1; k < NCRYS; k++)
            if (starts[k] <= v) c = k;
        if (c != cur) {
            if (cur >= 0) atomicAdd(&g_pool[cur * 128 + t], sum);
            sum = 0.f;
            cur = c;
        }
        sum += srcbuf[v * 64 + h];
    }
    if (cur >= 0) atomicAdd(&g_pool[cur * 128 + t], sum);
}

__global__ void fc_kernel(const int* __restrict__ crys,
                          const float* __restrict__ W,
                          const float* __restrict__ b,
                          float* __restrict__ out) {
    int t = threadIdx.x;
    if (t >= NCRYS * 2) return;
    int c = t >> 1, o = t & 1;
    float cnt = (float)(crys[c * 2 + 1] - crys[c * 2]);
    float inv = 1.0f / cnt;
    float s = 0.f;
    for (int h = 0; h < 128; h++)
        s += g_pool[c * 128 + h] * inv * W[h * 2 + o];
    out[t] = s + b[o];
}

// ---------------- launch -----------------------------------------------------
extern "C" void kernel_launch(void* const* d_in, const int* in_sizes, int n_in,
                              void* d_out, int out_size) {
    const float* bond     = (const float*)d_in[0];
    const float* angle    = (const float*)d_in[1];
    const int*   species  = (const int*)d_in[2];
    const int*   nbr      = (const int*)d_in[3];
    const int*   crys     = (const int*)d_in[4];
    const float* W1b_rel  = (const float*)d_in[5];
    const float* W1b_root = (const float*)d_in[6];
    const float* b1b      = (const float*)d_in[7];
    const float* W1a_rel  = (const float*)d_in[8];
    const float* W1a_root = (const float*)d_in[9];
    const float* b1a      = (const float*)d_in[10];
    const float* W2b_rel  = (const float*)d_in[11];
    const float* W2b_root = (const float*)d_in[12];
    const float* b2b      = (const float*)d_in[13];
    const float* W2a_rel  = (const float*)d_in[14];
    const float* W2a_root = (const float*)d_in[15];
    const float* b2a      = (const float*)d_in[16];
    const float* fcW      = (const float*)d_in[17];
    const float* fcb      = (const float*)d_in[18];
    float* out = (float*)d_out;

    float *Xp, *bfp, *afp;
    cudaGetSymbolAddress((void**)&Xp,  g_X);
    cudaGetSymbolAddress((void**)&bfp, g_bf);
    cudaGetSymbolAddress((void**)&afp, g_af);

    const int T = 256;
    dim3 ggrid((NN + 127) / 128, 4);

    zero_kernel<<<(NN * 3 + T - 1) / T, T>>>();
    count_kernel<<<(EE + T - 1) / T, T>>>(nbr, species);

    // --- bond stream, layer 1
    expand_bond<<<(NN * INB + T - 1) / T, T>>>(bond);
    gemm_kernel<<<ggrid, T>>>(Xp, INB, W1b_root, W1b_rel);
    init_acc<<<(NN * HD + T - 1) / T, T>>>(b1b);
    scatter_kernel<<<(EE * 64 + T - 1) / T, T>>>(nbr, species);
    relu_copy<<<(NN * HD + T - 1) / T, T>>>(bfp);

    // --- angle stream, layer 1
    expand_angle<<<(NN * INA + T - 1) / T, T>>>(angle);
    gemm_kernel<<<ggrid, T>>>(Xp, INA, W1a_root, W1a_rel);
    init_acc<<<(NN * HD + T - 1) / T, T>>>(b1a);
    scatter_kernel<<<(EE * 64 + T - 1) / T, T>>>(nbr, species);
    relu_copy<<<(NN * HD + T - 1) / T, T>>>(afp);

    // --- bond stream, layer 2
    gemm_kernel<<<ggrid, T>>>(bfp, HD, W2b_root, W2b_rel);
    init_acc<<<(NN * HD + T - 1) / T, T>>>(b2b);
    scatter_kernel<<<(EE * 64 + T - 1) / T, T>>>(nbr, species);
    relu_copy<<<(NN * HD + T - 1) / T, T>>>(bfp);

    // --- angle stream, layer 2
    gemm_kernel<<<ggrid, T>>>(afp, HD, W2a_root, W2a_rel);
    init_acc<<<(NN * HD + T - 1) / T, T>>>(b2a);
    scatter_kernel<<<(EE * 64 + T - 1) / T, T>>>(nbr, species);
    relu_copy<<<(NN * HD + T - 1) / T, T>>>(afp);

    // --- pooling + FC
    pool_kernel<<<(NN + POOL_NODES - 1) / POOL_NODES, 128>>>(crys);
    fc_kernel<<<1, 64>>>(crys, fcW, fcb, out);
}

// round 3
// speedup vs baseline: 1.4547x; 1.4547x over previous
#include <cuda_runtime.h>
#include <cuda_bf16.h>
#include <cstdint>

#define NN     20000
#define NEIGH  12
#define EE     (NN*NEIGH)
#define HD     64
#define INB    480
#define INA    2880
#define NCRYS  20

// ---------------- scratch ----------------------------------------------------
__device__ __align__(256) __nv_bfloat16 g_Xh[(size_t)NN * INA];
__device__ __align__(256) __nv_bfloat16 g_Xl[(size_t)NN * INA];
__device__ __align__(256) __nv_bfloat16 g_Wth[256 * INA];
__device__ __align__(256) __nv_bfloat16 g_Wtl[256 * INA];
__device__ float g_H[(size_t)NN * 256];
__device__ float g_acc[NN * HD];
__device__ float g_bf[NN * HD];
__device__ float g_af[NN * HD];
__device__ __align__(256) __nv_bfloat16 g_bfh[NN * HD], g_bfl[NN * HD];
__device__ __align__(256) __nv_bfloat16 g_afh[NN * HD], g_afl[NN * HD];
__device__ int   g_cnt[NN * 3];
__device__ float g_pool[NCRYS * 128];

// ---------------- helpers ------------------------------------------------------
__device__ __forceinline__ uint32_t smem_u32(const void* p) {
    uint32_t a;
    asm("{ .reg .u64 t; cvta.to.shared.u64 t, %1; cvt.u32.u64 %0, t; }"
        : "=r"(a) : "l"(p));
    return a;
}

__device__ __forceinline__ void cp16(uint32_t dst, const void* src, int sz) {
    asm volatile("cp.async.cg.shared.global [%0], [%1], 16, %2;"
                 :: "r"(dst), "l"(src), "r"(sz));
}

__device__ __forceinline__ void ldmx4(uint32_t* r, uint32_t addr) {
    asm volatile("ldmatrix.sync.aligned.m8n8.x4.shared.b16 {%0,%1,%2,%3}, [%4];"
                 : "=r"(r[0]), "=r"(r[1]), "=r"(r[2]), "=r"(r[3]) : "r"(addr));
}

__device__ __forceinline__ void mma16816(float* c, const uint32_t* a, const uint32_t* b) {
    asm volatile(
        "mma.sync.aligned.m16n8k16.row.col.f32.bf16.bf16.f32 "
        "{%0,%1,%2,%3}, {%4,%5,%6,%7}, {%8,%9}, {%0,%1,%2,%3};"
        : "+f"(c[0]), "+f"(c[1]), "+f"(c[2]), "+f"(c[3])
        : "r"(a[0]), "r"(a[1]), "r"(a[2]), "r"(a[3]), "r"(b[0]), "r"(b[1]));
}

// ---------------- mma.sync GEMM: g_H[M,256] = X[M,K] @ Wt[256,K]^T (bf16x3) ----
// CTA: 128(M) x 128(N), grid (157, 2). K-chunk 32, 2-stage cp.async pipeline.
// smem rows padded to 80B: conflict-free for ldmatrix (r*80 mod 128 -> 8 distinct 16B banks)
#define SM_AH 0
#define SM_AL 10240
#define SM_BH 20480
#define SM_BL 30720
#define STAGE 40960
#define SMEM_GEMM (2 * STAGE)

__device__ __forceinline__ void load_chunk(uint32_t sbase, int st, int c,
                                           const __nv_bfloat16* Ah, const __nv_bfloat16* Al,
                                           const __nv_bfloat16* Bh, const __nv_bfloat16* Bl,
                                           int K, int m0, int n0, int tid) {
    uint32_t sb = sbase + st * STAGE;
    int k0 = c * 32;
#pragma unroll
    for (int q = 0; q < 2; q++) {
        int j = tid + q * 256;
        int row = j >> 2, cc = j & 3;
        uint32_t doff = (uint32_t)(row * 80 + cc * 16);
        // A (predicated on row < NN)
        int gm = m0 + row;
        int gmc = gm < NN ? gm : 0;
        int sz = gm < NN ? 16 : 0;
        size_t aoff = (size_t)gmc * K + k0 + cc * 8;
        cp16(sb + SM_AH + doff, Ah + aoff, sz);
        cp16(sb + SM_AL + doff, Al + aoff, sz);
        // B (always in range: n0+row < 256)
        size_t boff = (size_t)(n0 + row) * K + k0 + cc * 8;
        cp16(sb + SM_BH + doff, Bh + boff, 16);
        cp16(sb + SM_BL + doff, Bl + boff, 16);
    }
    asm volatile("cp.async.commit_group;" ::: "memory");
}

__global__ __launch_bounds__(256, 1)
void gemm_mma(const __nv_bfloat16* __restrict__ Ah,
              const __nv_bfloat16* __restrict__ Al,
              const __nv_bfloat16* __restrict__ Bh,
              const __nv_bfloat16* __restrict__ Bl,
              int K) {
    extern __shared__ char smem[];
    uint32_t sbase = smem_u32(smem);
    int tid = threadIdx.x;
    int w = tid >> 5, l = tid & 31;
    int m0 = blockIdx.x * 128;
    int n0 = blockIdx.y * 128;
    int warp_m = (w >> 1) * 32;
    int warp_n = (w & 1) * 64;
    int nchunks = K >> 5;

    float acc[2][8][4];
#pragma unroll
    for (int i = 0; i < 2; i++)
#pragma unroll
        for (int j = 0; j < 8; j++)
#pragma unroll
            for (int q = 0; q < 4; q++) acc[i][j][q] = 0.f;

    // per-thread ldmatrix base offsets (within a stage, s=0)
    uint32_t a_off[2];   // per m-tile (add SM_AH/SM_AL + stage)
#pragma unroll
    for (int mt = 0; mt < 2; mt++)
        a_off[mt] = (uint32_t)((warp_m + mt * 16 + (l & 15)) * 80 + ((l >> 4) * 16));
    uint32_t b_off[4];   // per n-tile-pair
#pragma unroll
    for (int p = 0; p < 4; p++)
        b_off[p] = (uint32_t)((warp_n + p * 16 + (l & 7) + ((l >> 4) << 3)) * 80 +
                              (((l >> 3) & 1) * 16));

    load_chunk(sbase, 0, 0, Ah, Al, Bh, Bl, K, m0, n0, tid);

    for (int c = 0; c < nchunks; c++) {
        if (c + 1 < nchunks) {
            load_chunk(sbase, (c + 1) & 1, c + 1, Ah, Al, Bh, Bl, K, m0, n0, tid);
            asm volatile("cp.async.wait_group 1;" ::: "memory");
        } else {
            asm volatile("cp.async.wait_group 0;" ::: "memory");
        }
        __syncthreads();

        uint32_t sb = sbase + (uint32_t)((c & 1) * STAGE);
#pragma unroll
        for (int s = 0; s < 2; s++) {
            uint32_t af[2][2][4];          // [mt][hi/lo][4]
#pragma unroll
            for (int mt = 0; mt < 2; mt++) {
                ldmx4(af[mt][0], sb + SM_AH + a_off[mt] + s * 32);
                ldmx4(af[mt][1], sb + SM_AL + a_off[mt] + s * 32);
            }
            uint32_t bfr[2][8][2];         // [hi/lo][ntile][2]
#pragma unroll
            for (int p = 0; p < 4; p++) {
                uint32_t r[4];
                ldmx4(r, sb + SM_BH + b_off[p] + s * 32);
                bfr[0][2 * p][0] = r[0]; bfr[0][2 * p][1] = r[1];
                bfr[0][2 * p + 1][0] = r[2]; bfr[0][2 * p + 1][1] = r[3];
                ldmx4(r, sb + SM_BL + b_off[p] + s * 32);
                bfr[1][2 * p][0] = r[0]; bfr[1][2 * p][1] = r[1];
                bfr[1][2 * p + 1][0] = r[2]; bfr[1][2 * p + 1][1] = r[3];
            }
#pragma unroll
            for (int mt = 0; mt < 2; mt++)
#pragma unroll
                for (int nt = 0; nt < 8; nt++) {
                    mma16816(acc[mt][nt], af[mt][0], bfr[0][nt]);  // Ah*Bh
                    mma16816(acc[mt][nt], af[mt][0], bfr[1][nt]);  // Ah*Bl
                    mma16816(acc[mt][nt], af[mt][1], bfr[0][nt]);  // Al*Bh
                }
        }
        __syncthreads();
    }

    // epilogue
#pragma unroll
    for (int mt = 0; mt < 2; mt++) {
        int m1 = m0 + warp_m + mt * 16 + (l >> 2);
        int m2 = m1 + 8;
#pragma unroll
        for (int nt = 0; nt < 8; nt++) {
            int nc = n0 + warp_n + nt * 8 + 2 * (l & 3);
            if (m1 < NN)
                *(float2*)(g_H + (size_t)m1 * 256 + nc) =
                    make_float2(acc[mt][nt][0], acc[mt][nt][1]);
            if (m2 < NN)
                *(float2*)(g_H + (size_t)m2 * 256 + nc) =
                    make_float2(acc[mt][nt][2], acc[mt][nt][3]);
        }
    }
}

// ---------------- prep: transpose + bf16-split weights into Wt[256,K] ---------
__global__ void prep_w(const float* __restrict__ Wroot,
                       const float* __restrict__ Wrel, int K) {
    int idx = blockIdx.x * blockDim.x + threadIdx.x;
    if (idx >= 256 * K) return;
    int n = idx / K, k = idx % K;
    int cb = n >> 6, h = n & 63;
    float wv = (cb == 0) ? Wroot[(size_t)k * 64 + h]
                         : Wrel[(size_t)(cb - 1) * K * 64 + (size_t)k * 64 + h];
    __nv_bfloat16 hi = __float2bfloat16(wv);
    float lo = wv - __bfloat162float(hi);
    g_Wth[(size_t)n * K + k] = hi;
    g_Wtl[(size_t)n * K + k] = __float2bfloat16(lo);
}

// ---------------- expansions ---------------------------------------------------
__global__ void expand_bond(const float* __restrict__ bond) {
    int idx = blockIdx.x * blockDim.x + threadIdx.x;
    if (idx >= NN * INB) return;
    int v = idx / INB, p = idx % INB;
    int j = p / 40, s = p % 40;
    float d = bond[v * NEIGH + j];
    float f = (float)s * (8.0f / 39.0f);
    float t = d - f;
    float x = __expf(-t * t * 25.0f);
    __nv_bfloat16 hi = __float2bfloat16(x);
    g_Xh[(size_t)v * INB + p] = hi;
    g_Xl[(size_t)v * INB + p] = __float2bfloat16(x - __bfloat162float(hi));
}

__global__ void expand_angle(const float* __restrict__ ang) {
    int idx = blockIdx.x * blockDim.x + threadIdx.x;
    if (idx >= NN * INA) return;
    int jk = (idx % INA) / 20, s = idx % 20;
    float d = ang[(size_t)(idx / INA) * 144 + jk];
    float f = -1.0f + (float)s * (2.0f / 19.0f);
    float t = d - f;
    float x = __expf(-t * t * 100.0f);
    __nv_bfloat16 hi = __float2bfloat16(x);
    g_Xh[idx] = hi;
    g_Xl[idx] = __float2bfloat16(x - __bfloat162float(hi));
}

// ---------------- graph parts ---------------------------------------------------
__global__ void zero_kernel() {
    int i = blockIdx.x * blockDim.x + threadIdx.x;
    if (i < NN * 3) g_cnt[i] = 0;
    if (i < NCRYS * 128) g_pool[i] = 0.f;
}

__global__ void count_kernel(const int* __restrict__ nbr,
                             const int* __restrict__ species) {
    int e = blockIdx.x * blockDim.x + threadIdx.x;
    if (e >= EE) return;
    int src = e / NEIGH;
    int dst = nbr[e];
    int et = species[src] + species[dst];
    atomicAdd(&g_cnt[dst * 3 + et], 1);
}

__global__ void init_acc(const float* __restrict__ b) {
    int i = blockIdx.x * blockDim.x + threadIdx.x;
    if (i >= NN * HD) return;
    int h = i & 63;
    g_acc[i] = g_H[(size_t)(i >> 6) * 256 + h] + b[h];
}

__global__ void scatter_kernel(const int* __restrict__ nbr,
                               const int* __restrict__ species) {
    int idx = blockIdx.x * blockDim.x + threadIdx.x;
    if (idx >= EE * 64) return;
    int e = idx >> 6, h = idx & 63;
    int src = e / NEIGH;
    int dst = nbr[e];
    int et = species[src] + species[dst];
    int c = g_cnt[dst * 3 + et];
    if (c < 1) c = 1;
    float v = g_H[(size_t)src * 256 + (et + 1) * 64 + h] * (1.0f / (float)c);
    atomicAdd(&g_acc[dst * 64 + h], v);
}

__global__ void relu_split(float* __restrict__ f32dst,
                           __nv_bfloat16* __restrict__ hdst,
                           __nv_bfloat16* __restrict__ ldst) {
    int i = blockIdx.x * blockDim.x + threadIdx.x;
    if (i >= NN * HD) return;
    float v = g_acc[i];
    v = v > 0.f ? v : 0.f;
    f32dst[i] = v;
    __nv_bfloat16 hi = __float2bfloat16(v);
    hdst[i] = hi;
    ldst[i] = __float2bfloat16(v - __bfloat162float(hi));
}

__global__ void relu_copy(float* __restrict__ dstbuf) {
    int i = blockIdx.x * blockDim.x + threadIdx.x;
    if (i >= NN * HD) return;
    float v = g_acc[i];
    dstbuf[i] = v > 0.f ? v : 0.f;
}

#define POOL_NODES 160
__global__ void pool_kernel(const int* __restrict__ crys) {
    __shared__ int starts[NCRYS];
    int t = threadIdx.x;
    if (t < NCRYS) starts[t] = crys[t * 2];
    __syncthreads();
    int v0 = blockIdx.x * POOL_NODES;
    int v1 = v0 + POOL_NODES;
    if (v1 > NN) v1 = NN;
    const float* srcbuf = (t < 64) ? g_bf : g_af;
    int h = t & 63;
    float sum = 0.f;
    int cur = -2;
    for (int v = v0; v < v1; v++) {
        int c = 0;
#pragma unroll
        for (int k = 1; k < NCRYS; k++)
            if (starts[k] <= v) c = k;
        if (c != cur) {
            if (cur >= 0) atomicAdd(&g_pool[cur * 128 + t], sum);
            sum = 0.f;
            cur = c;
        }
        sum += srcbuf[v * 64 + h];
    }
    if (cur >= 0) atomicAdd(&g_pool[cur * 128 + t], sum);
}

__global__ void fc_kernel(const int* __restrict__ crys,
                          const float* __restrict__ W,
                          const float* __restrict__ b,
                          float* __restrict__ out) {
    int t = threadIdx.x;
    if (t >= NCRYS * 2) return;
    int c = t >> 1, o = t & 1;
    float cnt = (float)(crys[c * 2 + 1] - crys[c * 2]);
    float inv = 1.0f / cnt;
    float s = 0.f;
    for (int h = 0; h < 128; h++)
        s += g_pool[c * 128 + h] * inv * W[h * 2 + o];
    out[t] = s + b[o];
}

// ---------------- launch ---------------------------------------------------------
extern "C" void kernel_launch(void* const* d_in, const int* in_sizes, int n_in,
                              void* d_out, int out_size) {
    const float* bond     = (const float*)d_in[0];
    const float* angle    = (const float*)d_in[1];
    const int*   species  = (const int*)d_in[2];
    const int*   nbr      = (const int*)d_in[3];
    const int*   crys     = (const int*)d_in[4];
    const float* W1b_rel  = (const float*)d_in[5];
    const float* W1b_root = (const float*)d_in[6];
    const float* b1b      = (const float*)d_in[7];
    const float* W1a_rel  = (const float*)d_in[8];
    const float* W1a_root = (const float*)d_in[9];
    const float* b1a      = (const float*)d_in[10];
    const float* W2b_rel  = (const float*)d_in[11];
    const float* W2b_root = (const float*)d_in[12];
    const float* b2b      = (const float*)d_in[13];
    const float* W2a_rel  = (const float*)d_in[14];
    const float* W2a_root = (const float*)d_in[15];
    const float* b2a      = (const float*)d_in[16];
    const float* fcW      = (const float*)d_in[17];
    const float* fcb      = (const float*)d_in[18];
    float* out = (float*)d_out;

    cudaFuncSetAttribute(gemm_mma, cudaFuncAttributeMaxDynamicSharedMemorySize, SMEM_GEMM);

    __nv_bfloat16 *Xh, *Xl, *Wth, *Wtl, *bfh, *bfl, *afh, *afl;
    float *bfp, *afp;
    cudaGetSymbolAddress((void**)&Xh,  g_Xh);
    cudaGetSymbolAddress((void**)&Xl,  g_Xl);
    cudaGetSymbolAddress((void**)&Wth, g_Wth);
    cudaGetSymbolAddress((void**)&Wtl, g_Wtl);
    cudaGetSymbolAddress((void**)&bfh, g_bfh);
    cudaGetSymbolAddress((void**)&bfl, g_bfl);
    cudaGetSymbolAddress((void**)&afh, g_afh);
    cudaGetSymbolAddress((void**)&afl, g_afl);
    cudaGetSymbolAddress((void**)&bfp, g_bf);
    cudaGetSymbolAddress((void**)&afp, g_af);

    const int T = 256;
    dim3 ggrid((NN + 127) / 128, 2);   // (157, 2)

    zero_kernel<<<(NN * 3 + T - 1) / T, T>>>();
    count_kernel<<<(EE + T - 1) / T, T>>>(nbr, species);

    // --- bond, layer 1
    expand_bond<<<(NN * INB + T - 1) / T, T>>>(bond);
    prep_w<<<(256 * INB + T - 1) / T, T>>>(W1b_root, W1b_rel, INB);
    gemm_mma<<<ggrid, 256, SMEM_GEMM>>>(Xh, Xl, Wth, Wtl, INB);
    init_acc<<<(NN * HD + T - 1) / T, T>>>(b1b);
    scatter_kernel<<<(EE * 64 + T - 1) / T, T>>>(nbr, species);
    relu_split<<<(NN * HD + T - 1) / T, T>>>(bfp, bfh, bfl);

    // --- angle, layer 1
    expand_angle<<<(NN * INA + T - 1) / T, T>>>(angle);
    prep_w<<<(256 * INA + T - 1) / T, T>>>(W1a_root, W1a_rel, INA);
    gemm_mma<<<ggrid, 256, SMEM_GEMM>>>(Xh, Xl, Wth, Wtl, INA);
    init_acc<<<(NN * HD + T - 1) / T, T>>>(b1a);
    scatter_kernel<<<(EE * 64 + T - 1) / T, T>>>(nbr, species);
    relu_split<<<(NN * HD + T - 1) / T, T>>>(afp, afh, afl);

    // --- bond, layer 2
    prep_w<<<(256 * HD + T - 1) / T, T>>>(W2b_root, W2b_rel, HD);
    gemm_mma<<<ggrid, 256, SMEM_GEMM>>>(bfh, bfl, Wth, Wtl, HD);
    init_acc<<<(NN * HD + T - 1) / T, T>>>(b2b);
    scatter_kernel<<<(EE * 64 + T - 1) / T, T>>>(nbr, species);
    relu_copy<<<(NN * HD + T - 1) / T, T>>>(bfp);

    // --- angle, layer 2
    prep_w<<<(256 * HD + T - 1) / T, T>>>(W2a_root, W2a_rel, HD);
    gemm_mma<<<ggrid, 256, SMEM_GEMM>>>(afh, afl, Wth, Wtl, HD);
    init_acc<<<(NN * HD + T - 1) / T, T>>>(b2a);
    scatter_kernel<<<(EE * 64 + T - 1) / T, T>>>(nbr, species);
    relu_copy<<<(NN * HD + T - 1) / T, T>>>(afp);

    // --- pooling + FC
    pool_kernel<<<(NN + POOL_NODES - 1) / POOL_NODES, 128>>>(crys);
    fc_kernel<<<1, 64>>>(crys, fcW, fcb, out);
}

// round 4
// speedup vs baseline: 1.5230x; 1.0469x over previous
#include <cuda_runtime.h>
#include <cuda_bf16.h>
#include <cstdint>

#define NN     20000
#define NEIGH  12
#define EE     (NN*NEIGH)
#define HD     64
#define INB    480
#define INA    2880
#define NCRYS  20

// ---------------- scratch ----------------------------------------------------
__device__ __align__(256) __nv_bfloat16 g_Wth[256 * INA];
__device__ __align__(256) __nv_bfloat16 g_Wtl[256 * INA];
__device__ float g_H[(size_t)NN * 256];
__device__ float g_bf[NN * HD];
__device__ float g_af[NN * HD];
__device__ __align__(256) __nv_bfloat16 g_bfh[NN * HD], g_bfl[NN * HD];
__device__ __align__(256) __nv_bfloat16 g_afh[NN * HD], g_afl[NN * HD];
__device__ int   g_cnt[NN * 3];
__device__ int   g_deg[NN];
__device__ int   g_off[NN + 1];
__device__ int   g_pos[NN];
__device__ int   g_rev[EE];          // packed src<<2 | etype
__device__ float g_pool[NCRYS * 128];

// ---------------- helpers ------------------------------------------------------
__device__ __forceinline__ uint32_t smem_u32(const void* p) {
    uint32_t a;
    asm("{ .reg .u64 t; cvta.to.shared.u64 t, %1; cvt.u32.u64 %0, t; }"
        : "=r"(a) : "l"(p));
    return a;
}

__device__ __forceinline__ void cp16(uint32_t dst, const void* src, int sz) {
    asm volatile("cp.async.cg.shared.global [%0], [%1], 16, %2;"
                 :: "r"(dst), "l"(src), "r"(sz));
}

__device__ __forceinline__ void ldmx4(uint32_t* r, uint32_t addr) {
    asm volatile("ldmatrix.sync.aligned.m8n8.x4.shared.b16 {%0,%1,%2,%3}, [%4];"
                 : "=r"(r[0]), "=r"(r[1]), "=r"(r[2]), "=r"(r[3]) : "r"(addr));
}

__device__ __forceinline__ void mma16816(float* c, const uint32_t* a, const uint32_t* b) {
    asm volatile(
        "mma.sync.aligned.m16n8k16.row.col.f32.bf16.bf16.f32 "
        "{%0,%1,%2,%3}, {%4,%5,%6,%7}, {%8,%9}, {%0,%1,%2,%3};"
        : "+f"(c[0]), "+f"(c[1]), "+f"(c[2]), "+f"(c[3])
        : "r"(a[0]), "r"(a[1]), "r"(a[2]), "r"(a[3]), "r"(b[0]), "r"(b[1]));
}

// ---------------- GEMM: g_H[M,256] = X[M,K] @ Wt[256,K]^T (bf16x3) -------------
// MODE 0: A from bf16 hi/lo buffers. MODE 1: bond expansion fused.
// MODE 2: angle expansion fused.
#define SM_AH 0
#define SM_AL 10240
#define SM_BH 20480
#define SM_BL 30720
#define STAGE 40960
#define SMEM_GEMM (2 * STAGE)

__device__ __forceinline__ void loadB_async(uint32_t sb, int c,
                                            const __nv_bfloat16* Bh,
                                            const __nv_bfloat16* Bl,
                                            int K, int n0, int tid) {
#pragma unroll
    for (int q = 0; q < 2; q++) {
        int j = tid + q * 256;
        int row = j >> 2, cc = j & 3;
        uint32_t doff = (uint32_t)(row * 80 + cc * 16);
        size_t boff = (size_t)(n0 + row) * K + c * 32 + cc * 8;
        cp16(sb + SM_BH + doff, Bh + boff, 16);
        cp16(sb + SM_BL + doff, Bl + boff, 16);
    }
}

__device__ __forceinline__ void loadA_async(uint32_t sb, int c,
                                            const __nv_bfloat16* Ah,
                                            const __nv_bfloat16* Al,
                                            int K, int m0, int tid) {
#pragma unroll
    for (int q = 0; q < 2; q++) {
        int j = tid + q * 256;
        int row = j >> 2, cc = j & 3;
        uint32_t doff = (uint32_t)(row * 80 + cc * 16);
        int gm = m0 + row;
        int gmc = gm < NN ? gm : 0;
        int sz = gm < NN ? 16 : 0;
        size_t aoff = (size_t)gmc * K + c * 32 + cc * 8;
        cp16(sb + SM_AH + doff, Ah + aoff, sz);
        cp16(sb + SM_AL + doff, Al + aoff, sz);
    }
}

template<int MODE>
__device__ __forceinline__ void fillA_expand(char* st, int c, const float* src,
                                             int m0, int tid) {
    int row = tid >> 1;
    int kb  = (tid & 1) * 16;
    int gr  = m0 + row;
    uint32_t hb[8], lb[8];
    if (gr < NN) {
#pragma unroll
        for (int i = 0; i < 8; i++) {
            float xs[2];
#pragma unroll
            for (int q = 0; q < 2; q++) {
                int k = c * 32 + kb + i * 2 + q;
                float x;
                if (MODE == 1) {
                    int j = k / 40, s = k - j * 40;
                    float d = src[gr * NEIGH + j];
                    float t = d - (float)s * (8.0f / 39.0f);
                    x = __expf(-t * t * 25.0f);
                } else {
                    int j = k / 20, s = k - j * 20;
                    float d = src[gr * 144 + j];
                    float t = d - (-1.0f + (float)s * (2.0f / 19.0f));
                    x = __expf(-t * t * 100.0f);
                }
                xs[q] = x;
            }
            __nv_bfloat16 h0 = __float2bfloat16(xs[0]);
            __nv_bfloat16 h1 = __float2bfloat16(xs[1]);
            __nv_bfloat16 l0 = __float2bfloat16(xs[0] - __bfloat162float(h0));
            __nv_bfloat16 l1 = __float2bfloat16(xs[1] - __bfloat162float(h1));
            hb[i] = ((uint32_t)__bfloat16_as_ushort(h1) << 16) | __bfloat16_as_ushort(h0);
            lb[i] = ((uint32_t)__bfloat16_as_ushort(l1) << 16) | __bfloat16_as_ushort(l0);
        }
    } else {
#pragma unroll
        for (int i = 0; i < 8; i++) { hb[i] = 0u; lb[i] = 0u; }
    }
    uint32_t doff = (uint32_t)(row * 80 + kb * 2);
    *(uint4*)(st + SM_AH + doff)      = make_uint4(hb[0], hb[1], hb[2], hb[3]);
    *(uint4*)(st + SM_AH + doff + 16) = make_uint4(hb[4], hb[5], hb[6], hb[7]);
    *(uint4*)(st + SM_AL + doff)      = make_uint4(lb[0], lb[1], lb[2], lb[3]);
    *(uint4*)(st + SM_AL + doff + 16) = make_uint4(lb[4], lb[5], lb[6], lb[7]);
}

template<int MODE>
__global__ __launch_bounds__(256, 1)
void gemm_mma(const void* A0v, const void* A1v,
              const __nv_bfloat16* __restrict__ Bh,
              const __nv_bfloat16* __restrict__ Bl,
              int K) {
    extern __shared__ char smem[];
    uint32_t sbase = smem_u32(smem);
    int tid = threadIdx.x;
    int w = tid >> 5, l = tid & 31;
    int m0 = blockIdx.x * 128;
    int n0 = blockIdx.y * 128;
    int warp_m = (w >> 1) * 32;
    int warp_n = (w & 1) * 64;
    int nchunks = K >> 5;

    float acc[2][8][4];
#pragma unroll
    for (int i = 0; i < 2; i++)
#pragma unroll
        for (int j = 0; j < 8; j++)
#pragma unroll
            for (int q = 0; q < 4; q++) acc[i][j][q] = 0.f;

    uint32_t a_off[2];
#pragma unroll
    for (int mt = 0; mt < 2; mt++)
        a_off[mt] = (uint32_t)((warp_m + mt * 16 + (l & 15)) * 80 + ((l >> 4) * 16));
    uint32_t b_off[4];
#pragma unroll
    for (int p = 0; p < 4; p++)
        b_off[p] = (uint32_t)((warp_n + p * 16 + (l & 7) + ((l >> 4) << 3)) * 80 +
                              (((l >> 3) & 1) * 16));

    // prologue: stage 0, chunk 0
    {
        loadB_async(sbase, 0, Bh, Bl, K, n0, tid);
        if (MODE == 0)
            loadA_async(sbase, 0, (const __nv_bfloat16*)A0v,
                        (const __nv_bfloat16*)A1v, K, m0, tid);
        asm volatile("cp.async.commit_group;" ::: "memory");
        if (MODE != 0)
            fillA_expand<MODE>(smem, 0, (const float*)A0v, m0, tid);
    }

    for (int c = 0; c < nchunks; c++) {
        if (c + 1 < nchunks) {
            int st = (c + 1) & 1;
            uint32_t sb = sbase + st * STAGE;
            loadB_async(sb, c + 1, Bh, Bl, K, n0, tid);
            if (MODE == 0)
                loadA_async(sb, c + 1, (const __nv_bfloat16*)A0v,
                            (const __nv_bfloat16*)A1v, K, m0, tid);
            asm volatile("cp.async.commit_group;" ::: "memory");
            if (MODE != 0)
                fillA_expand<MODE>(smem + st * STAGE, c + 1, (const float*)A0v, m0, tid);
            asm volatile("cp.async.wait_group 1;" ::: "memory");
        } else {
            asm volatile("cp.async.wait_group 0;" ::: "memory");
        }
        __syncthreads();

        uint32_t sb = sbase + (uint32_t)((c & 1) * STAGE);
#pragma unroll
        for (int s = 0; s < 2; s++) {
            uint32_t af[2][2][4];
#pragma unroll
            for (int mt = 0; mt < 2; mt++) {
                ldmx4(af[mt][0], sb + SM_AH + a_off[mt] + s * 32);
                ldmx4(af[mt][1], sb + SM_AL + a_off[mt] + s * 32);
            }
            uint32_t bfr[2][8][2];
#pragma unroll
            for (int p = 0; p < 4; p++) {
                uint32_t r[4];
                ldmx4(r, sb + SM_BH + b_off[p] + s * 32);
                bfr[0][2 * p][0] = r[0]; bfr[0][2 * p][1] = r[1];
                bfr[0][2 * p + 1][0] = r[2]; bfr[0][2 * p + 1][1] = r[3];
                ldmx4(r, sb + SM_BL + b_off[p] + s * 32);
                bfr[1][2 * p][0] = r[0]; bfr[1][2 * p][1] = r[1];
                bfr[1][2 * p + 1][0] = r[2]; bfr[1][2 * p + 1][1] = r[3];
            }
#pragma unroll
            for (int mt = 0; mt < 2; mt++)
#pragma unroll
                for (int nt = 0; nt < 8; nt++) {
                    mma16816(acc[mt][nt], af[mt][0], bfr[0][nt]);
                    mma16816(acc[mt][nt], af[mt][0], bfr[1][nt]);
                    mma16816(acc[mt][nt], af[mt][1], bfr[0][nt]);
                }
        }
        __syncthreads();
    }

#pragma unroll
    for (int mt = 0; mt < 2; mt++) {
        int m1 = m0 + warp_m + mt * 16 + (l >> 2);
        int m2 = m1 + 8;
#pragma unroll
        for (int nt = 0; nt < 8; nt++) {
            int nc = n0 + warp_n + nt * 8 + 2 * (l & 3);
            if (m1 < NN)
                *(float2*)(g_H + (size_t)m1 * 256 + nc) =
                    make_float2(acc[mt][nt][0], acc[mt][nt][1]);
            if (m2 < NN)
                *(float2*)(g_H + (size_t)m2 * 256 + nc) =
                    make_float2(acc[mt][nt][2], acc[mt][nt][3]);
        }
    }
}

// ---------------- weight transpose + bf16 split (smem-tiled) -------------------
__global__ void prep_wT(const float* __restrict__ Wroot,
                        const float* __restrict__ Wrel, int K) {
    __shared__ float sm[32][65];
    int tid = threadIdx.x;
    int k0 = blockIdx.x * 32;
    int cb = blockIdx.y;
#pragma unroll
    for (int i = 0; i < 8; i++) {
        int e = tid + i * 256;
        int k = e >> 6, h = e & 63;
        float wv = (cb == 0) ? Wroot[(size_t)(k0 + k) * 64 + h]
                             : Wrel[(size_t)(cb - 1) * K * 64 + (size_t)(k0 + k) * 64 + h];
        sm[k][h] = wv;
    }
    __syncthreads();
#pragma unroll
    for (int i = 0; i < 8; i++) {
        int e = tid + i * 256;
        int h = e >> 5, kk = e & 31;
        float wv = sm[kk][h];
        __nv_bfloat16 hi = __float2bfloat16(wv);
        float lo = wv - __bfloat162float(hi);
        size_t o = (size_t)(cb * 64 + h) * K + k0 + kk;
        g_Wth[o] = hi;
        g_Wtl[o] = __float2bfloat16(lo);
    }
}

// ---------------- graph preprocessing ------------------------------------------
__global__ void zero_kernel() {
    int i = blockIdx.x * blockDim.x + threadIdx.x;
    if (i < NN * 3) g_cnt[i] = 0;
    if (i < NN) g_deg[i] = 0;
    if (i < NCRYS * 128) g_pool[i] = 0.f;
}

__global__ void count_kernel(const int* __restrict__ nbr,
                             const int* __restrict__ species) {
    int e = blockIdx.x * blockDim.x + threadIdx.x;
    if (e >= EE) return;
    int src = e / NEIGH;
    int dst = nbr[e];
    int et = species[src] + species[dst];
    atomicAdd(&g_cnt[dst * 3 + et], 1);
    atomicAdd(&g_deg[dst], 1);
}

__global__ void scan_kernel() {
    __shared__ int ps[1024];
    int t = threadIdx.x;
    int base = t * 20;
    int local[20];
    int s = 0;
#pragma unroll
    for (int i = 0; i < 20; i++) {
        int idx = base + i;
        int d = (idx < NN) ? g_deg[idx] : 0;
        local[i] = s;
        s += d;
    }
    ps[t] = s;
    __syncthreads();
    for (int off = 1; off < 1024; off <<= 1) {
        int v = (t >= off) ? ps[t - off] : 0;
        __syncthreads();
        ps[t] += v;
        __syncthreads();
    }
    int pre = (t > 0) ? ps[t - 1] : 0;
#pragma unroll
    for (int i = 0; i < 20; i++) {
        int idx = base + i;
        if (idx < NN) {
            g_off[idx] = pre + local[i];
            g_pos[idx] = pre + local[i];
        }
    }
    if (t == 1023) g_off[NN] = ps[1023];
}

__global__ void fill_kernel(const int* __restrict__ nbr,
                            const int* __restrict__ species) {
    int e = blockIdx.x * blockDim.x + threadIdx.x;
    if (e >= EE) return;
    int src = e / NEIGH;
    int dst = nbr[e];
    int et = species[src] + species[dst];
    int p = atomicAdd(&g_pos[dst], 1);
    g_rev[p] = (src << 2) | et;
}

// ---------------- gather aggregation (fused bias + relu + output) --------------
// OUT=0: write bf16 hi/lo; OUT=1: write f32.
template<int OUT>
__global__ void gather_kernel(const float* __restrict__ bias,
                              __nv_bfloat16* __restrict__ oh,
                              __nv_bfloat16* __restrict__ ol,
                              float* __restrict__ of) {
    int tid = threadIdx.x;
    int dst = blockIdx.x * 4 + (tid >> 6);
    int h = tid & 63;
    if (dst >= NN) return;
    int c0 = g_cnt[dst * 3 + 0], c1 = g_cnt[dst * 3 + 1], c2 = g_cnt[dst * 3 + 2];
    float inv0 = 1.0f / (float)(c0 > 0 ? c0 : 1);
    float inv1 = 1.0f / (float)(c1 > 0 ? c1 : 1);
    float inv2 = 1.0f / (float)(c2 > 0 ? c2 : 1);
    float v = g_H[(size_t)dst * 256 + h] + bias[h];
    int b0 = g_off[dst], b1 = g_off[dst + 1];
    for (int p = b0; p < b1; p++) {
        int pk = g_rev[p];
        int src = pk >> 2, et = pk & 3;
        float ic = (et == 0) ? inv0 : ((et == 1) ? inv1 : inv2);
        v += g_H[(size_t)src * 256 + (et + 1) * 64 + h] * ic;
    }
    v = v > 0.f ? v : 0.f;
    if (OUT == 0) {
        __nv_bfloat16 hi = __float2bfloat16(v);
        oh[dst * 64 + h] = hi;
        ol[dst * 64 + h] = __float2bfloat16(v - __bfloat162float(hi));
    } else {
        of[dst * 64 + h] = v;
    }
}

// ---------------- pooling + FC ---------------------------------------------------
#define POOL_NODES 160
__global__ void pool_kernel(const int* __restrict__ crys) {
    __shared__ int starts[NCRYS];
    int t = threadIdx.x;
    if (t < NCRYS) starts[t] = crys[t * 2];
    __syncthreads();
    int v0 = blockIdx.x * POOL_NODES;
    int v1 = v0 + POOL_NODES;
    if (v1 > NN) v1 = NN;
    const float* srcbuf = (t < 64) ? g_bf : g_af;
    int h = t & 63;
    float sum = 0.f;
    int cur = -2;
    for (int v = v0; v < v1; v++) {
        int c = 0;
#pragma unroll
        for (int k = 1; k < NCRYS; k++)
            if (starts[k] <= v) c = k;
        if (c != cur) {
            if (cur >= 0) atomicAdd(&g_pool[cur * 128 + t], sum);
            sum = 0.f;
            cur = c;
        }
        sum += srcbuf[v * 64 + h];
    }
    if (cur >= 0) atomicAdd(&g_pool[cur * 128 + t], sum);
}

__global__ void fc_kernel(const int* __restrict__ crys,
                          const float* __restrict__ W,
                          const float* __restrict__ b,
                          float* __restrict__ out) {
    int t = threadIdx.x;
    if (t >= NCRYS * 2) return;
    int c = t >> 1, o = t & 1;
    float cnt = (float)(crys[c * 2 + 1] - crys[c * 2]);
    float inv = 1.0f / cnt;
    float s = 0.f;
    for (int h = 0; h < 128; h++)
        s += g_pool[c * 128 + h] * inv * W[h * 2 + o];
    out[t] = s + b[o];
}

// ---------------- launch ----------------------------------------------------------
extern "C" void kernel_launch(void* const* d_in, const int* in_sizes, int n_in,
                              void* d_out, int out_size) {
    const float* bond     = (const float*)d_in[0];
    const float* angle    = (const float*)d_in[1];
    const int*   species  = (const int*)d_in[2];
    const int*   nbr      = (const int*)d_in[3];
    const int*   crys     = (const int*)d_in[4];
    const float* W1b_rel  = (const float*)d_in[5];
    const float* W1b_root = (const float*)d_in[6];
    const float* b1b      = (const float*)d_in[7];
    const float* W1a_rel  = (const float*)d_in[8];
    const float* W1a_root = (const float*)d_in[9];
    const float* b1a      = (const float*)d_in[10];
    const float* W2b_rel  = (const float*)d_in[11];
    const float* W2b_root = (const float*)d_in[12];
    const float* b2b      = (const float*)d_in[13];
    const float* W2a_rel  = (const float*)d_in[14];
    const float* W2a_root = (const float*)d_in[15];
    const float* b2a      = (const float*)d_in[16];
    const float* fcW      = (const float*)d_in[17];
    const float* fcb      = (const float*)d_in[18];
    float* out = (float*)d_out;

    cudaFuncSetAttribute(gemm_mma<0>, cudaFuncAttributeMaxDynamicSharedMemorySize, SMEM_GEMM);
    cudaFuncSetAttribute(gemm_mma<1>, cudaFuncAttributeMaxDynamicSharedMemorySize, SMEM_GEMM);
    cudaFuncSetAttribute(gemm_mma<2>, cudaFuncAttributeMaxDynamicSharedMemorySize, SMEM_GEMM);

    __nv_bfloat16 *Wth, *Wtl, *bfh, *bfl, *afh, *afl;
    float *bfp, *afp;
    cudaGetSymbolAddress((void**)&Wth, g_Wth);
    cudaGetSymbolAddress((void**)&Wtl, g_Wtl);
    cudaGetSymbolAddress((void**)&bfh, g_bfh);
    cudaGetSymbolAddress((void**)&bfl, g_bfl);
    cudaGetSymbolAddress((void**)&afh, g_afh);
    cudaGetSymbolAddress((void**)&afl, g_afl);
    cudaGetSymbolAddress((void**)&bfp, g_bf);
    cudaGetSymbolAddress((void**)&afp, g_af);

    const int T = 256;
    dim3 ggrid((NN + 127) / 128, 2);
    const int GGRID = (NN + 3) / 4;   // 5000 gather blocks

    // graph preprocessing (once, reused by all 4 layers)
    zero_kernel<<<(NN * 3 + T - 1) / T, T>>>();
    count_kernel<<<(EE + T - 1) / T, T>>>(nbr, species);
    scan_kernel<<<1, 1024>>>();
    fill_kernel<<<(EE + T - 1) / T, T>>>(nbr, species);

    // --- bond, layer 1 (fused expansion)
    prep_wT<<<dim3(INB / 32, 4), 256>>>(W1b_root, W1b_rel, INB);
    gemm_mma<1><<<ggrid, 256, SMEM_GEMM>>>(bond, nullptr, Wth, Wtl, INB);
    gather_kernel<0><<<GGRID, 256>>>(b1b, bfh, bfl, nullptr);

    // --- angle, layer 1 (fused expansion)
    prep_wT<<<dim3(INA / 32, 4), 256>>>(W1a_root, W1a_rel, INA);
    gemm_mma<2><<<ggrid, 256, SMEM_GEMM>>>(angle, nullptr, Wth, Wtl, INA);
    gather_kernel<0><<<GGRID, 256>>>(b1a, afh, afl, nullptr);

    // --- bond, layer 2
    prep_wT<<<dim3(HD / 32, 4), 256>>>(W2b_root, W2b_rel, HD);
    gemm_mma<0><<<ggrid, 256, SMEM_GEMM>>>(bfh, bfl, Wth, Wtl, HD);
    gather_kernel<1><<<GGRID, 256>>>(b2b, nullptr, nullptr, bfp);

    // --- angle, layer 2
    prep_wT<<<dim3(HD / 32, 4), 256>>>(W2a_root, W2a_rel, HD);
    gemm_mma<0><<<ggrid, 256, SMEM_GEMM>>>(afh, afl, Wth, Wtl, HD);
    gather_kernel<1><<<GGRID, 256>>>(b2a, nullptr, nullptr, afp);

    // --- pooling + FC
    pool_kernel<<<(NN + POOL_NODES - 1) / POOL_NODES, 128>>>(crys);
    fc_kernel<<<1, 64>>>(crys, fcW, fcb, out);
}

// round 5
// speedup vs baseline: 1.5332x; 1.0067x over previous
#include <cuda_runtime.h>
#include <cuda_bf16.h>
#include <cstdint>

#define NN     20000
#define NEIGH  12
#define EE     (NN*NEIGH)
#define HD     64
#define INB    480
#define INA    2880
#define NCRYS  20

// ---------------- scratch ----------------------------------------------------
__device__ __align__(256) __nv_bfloat16 g_Wth[256 * INA];
__device__ __align__(256) __nv_bfloat16 g_Wtl[256 * INA];
__device__ float g_H[(size_t)NN * 256];
__device__ float g_bf[NN * HD];
__device__ float g_af[NN * HD];
__device__ __align__(256) __nv_bfloat16 g_bfh[NN * HD], g_bfl[NN * HD];
__device__ __align__(256) __nv_bfloat16 g_afh[NN * HD], g_afl[NN * HD];
__device__ int   g_cnt[NN * 3];
__device__ int   g_deg[NN];
__device__ int   g_off[NN + 1];
__device__ int   g_pos[NN];
__device__ int   g_rev[EE];          // packed src<<2 | etype
__device__ float g_pool[NCRYS * 128];

// ---------------- helpers ------------------------------------------------------
__device__ __forceinline__ uint32_t smem_u32(const void* p) {
    uint32_t a;
    asm("{ .reg .u64 t; cvta.to.shared.u64 t, %1; cvt.u32.u64 %0, t; }"
        : "=r"(a) : "l"(p));
    return a;
}

__device__ __forceinline__ void cp16(uint32_t dst, const void* src, int sz) {
    asm volatile("cp.async.cg.shared.global [%0], [%1], 16, %2;"
                 :: "r"(dst), "l"(src), "r"(sz));
}

__device__ __forceinline__ void ldmx4(uint32_t* r, uint32_t addr) {
    asm volatile("ldmatrix.sync.aligned.m8n8.x4.shared.b16 {%0,%1,%2,%3}, [%4];"
                 : "=r"(r[0]), "=r"(r[1]), "=r"(r[2]), "=r"(r[3]) : "r"(addr));
}

__device__ __forceinline__ void mma16816(float* c, const uint32_t* a, const uint32_t* b) {
    asm volatile(
        "mma.sync.aligned.m16n8k16.row.col.f32.bf16.bf16.f32 "
        "{%0,%1,%2,%3}, {%4,%5,%6,%7}, {%8,%9}, {%0,%1,%2,%3};"
        : "+f"(c[0]), "+f"(c[1]), "+f"(c[2]), "+f"(c[3])
        : "r"(a[0]), "r"(a[1]), "r"(a[2]), "r"(a[3]), "r"(b[0]), "r"(b[1]));
}

// ---------------- GEMM: g_H[M,256] = X[M,K] @ Wt[256,K]^T (bf16x3) -------------
// CTA tile 128(M) x 256(N)  -> grid = 157 blocks = 1.06 waves on 148 SMs.
// K-chunk 32, 2-stage cp.async pipeline. smem rows padded to 80B (conflict-free
// for ldmatrix: r*80 mod 128 covers all 8 16B banks within each 8-row group).
// MODE 0: A from bf16 hi/lo buffers. MODE 1: bond expansion fused. MODE 2: angle.
#define SM_AH 0
#define SM_AL 10240
#define SM_BH 20480
#define SM_BL 40960
#define STAGE 61440
#define SMEM_GEMM (2 * STAGE)

__device__ __forceinline__ void loadB_async(uint32_t sb, int c,
                                            const __nv_bfloat16* Bh,
                                            const __nv_bfloat16* Bl,
                                            int K, int tid) {
#pragma unroll
    for (int q = 0; q < 4; q++) {
        int j = tid + q * 256;
        int row = j >> 2, cc = j & 3;
        uint32_t doff = (uint32_t)(row * 80 + cc * 16);
        size_t boff = (size_t)row * K + c * 32 + cc * 8;
        cp16(sb + SM_BH + doff, Bh + boff, 16);
        cp16(sb + SM_BL + doff, Bl + boff, 16);
    }
}

__device__ __forceinline__ void loadA_async(uint32_t sb, int c,
                                            const __nv_bfloat16* Ah,
                                            const __nv_bfloat16* Al,
                                            int K, int m0, int tid) {
#pragma unroll
    for (int q = 0; q < 2; q++) {
        int j = tid + q * 256;
        int row = j >> 2, cc = j & 3;
        uint32_t doff = (uint32_t)(row * 80 + cc * 16);
        int gm = m0 + row;
        int gmc = gm < NN ? gm : 0;
        int sz = gm < NN ? 16 : 0;
        size_t aoff = (size_t)gmc * K + c * 32 + cc * 8;
        cp16(sb + SM_AH + doff, Ah + aoff, sz);
        cp16(sb + SM_AL + doff, Al + aoff, sz);
    }
}

template<int MODE>
__device__ __forceinline__ void fillA_expand(char* st, int c, const float* src,
                                             int m0, int tid) {
    int row = tid >> 1;
    int kb  = (tid & 1) * 16;
    int gr  = m0 + row;
    uint32_t hb[8], lb[8];
    if (gr < NN) {
#pragma unroll
        for (int i = 0; i < 8; i++) {
            float xs[2];
#pragma unroll
            for (int q = 0; q < 2; q++) {
                int k = c * 32 + kb + i * 2 + q;
                float x;
                if (MODE == 1) {
                    int j = k / 40, s = k - j * 40;
                    float d = src[gr * NEIGH + j];
                    float t = d - (float)s * (8.0f / 39.0f);
                    x = __expf(-t * t * 25.0f);
                } else {
                    int j = k / 20, s = k - j * 20;
                    float d = src[gr * 144 + j];
                    float t = d - (-1.0f + (float)s * (2.0f / 19.0f));
                    x = __expf(-t * t * 100.0f);
                }
                xs[q] = x;
            }
            __nv_bfloat16 h0 = __float2bfloat16(xs[0]);
            __nv_bfloat16 h1 = __float2bfloat16(xs[1]);
            __nv_bfloat16 l0 = __float2bfloat16(xs[0] - __bfloat162float(h0));
            __nv_bfloat16 l1 = __float2bfloat16(xs[1] - __bfloat162float(h1));
            hb[i] = ((uint32_t)__bfloat16_as_ushort(h1) << 16) | __bfloat16_as_ushort(h0);
            lb[i] = ((uint32_t)__bfloat16_as_ushort(l1) << 16) | __bfloat16_as_ushort(l0);
        }
    } else {
#pragma unroll
        for (int i = 0; i < 8; i++) { hb[i] = 0u; lb[i] = 0u; }
    }
    uint32_t doff = (uint32_t)(row * 80 + kb * 2);
    *(uint4*)(st + SM_AH + doff)      = make_uint4(hb[0], hb[1], hb[2], hb[3]);
    *(uint4*)(st + SM_AH + doff + 16) = make_uint4(hb[4], hb[5], hb[6], hb[7]);
    *(uint4*)(st + SM_AL + doff)      = make_uint4(lb[0], lb[1], lb[2], lb[3]);
    *(uint4*)(st + SM_AL + doff + 16) = make_uint4(lb[4], lb[5], lb[6], lb[7]);
}

template<int MODE>
__global__ __launch_bounds__(256, 1)
void gemm_mma(const void* A0v, const void* A1v,
              const __nv_bfloat16* __restrict__ Bh,
              const __nv_bfloat16* __restrict__ Bl,
              int K) {
    extern __shared__ char smem[];
    uint32_t sbase = smem_u32(smem);
    int tid = threadIdx.x;
    int w = tid >> 5, l = tid & 31;
    int m0 = blockIdx.x * 128;
    int warp_m = (w >> 1) * 32;
    int warp_n = (w & 1) * 128;
    int nchunks = K >> 5;

    float acc[2][16][4];
#pragma unroll
    for (int i = 0; i < 2; i++)
#pragma unroll
        for (int j = 0; j < 16; j++)
#pragma unroll
            for (int q = 0; q < 4; q++) acc[i][j][q] = 0.f;

    uint32_t a_off[2];
#pragma unroll
    for (int mt = 0; mt < 2; mt++)
        a_off[mt] = (uint32_t)((warp_m + mt * 16 + (l & 15)) * 80 + ((l >> 4) * 16));
    uint32_t b_base = (uint32_t)((warp_n + (l & 7) + ((l >> 4) << 3)) * 80 +
                                 (((l >> 3) & 1) * 16));

    // prologue: stage 0, chunk 0
    {
        loadB_async(sbase, 0, Bh, Bl, K, tid);
        if (MODE == 0)
            loadA_async(sbase, 0, (const __nv_bfloat16*)A0v,
                        (const __nv_bfloat16*)A1v, K, m0, tid);
        asm volatile("cp.async.commit_group;" ::: "memory");
        if (MODE != 0)
            fillA_expand<MODE>(smem, 0, (const float*)A0v, m0, tid);
    }

    for (int c = 0; c < nchunks; c++) {
        if (c + 1 < nchunks) {
            int st = (c + 1) & 1;
            uint32_t sb = sbase + st * STAGE;
            loadB_async(sb, c + 1, Bh, Bl, K, tid);
            if (MODE == 0)
                loadA_async(sb, c + 1, (const __nv_bfloat16*)A0v,
                            (const __nv_bfloat16*)A1v, K, m0, tid);
            asm volatile("cp.async.commit_group;" ::: "memory");
            if (MODE != 0)
                fillA_expand<MODE>(smem + st * STAGE, c + 1, (const float*)A0v, m0, tid);
            asm volatile("cp.async.wait_group 1;" ::: "memory");
        } else {
            asm volatile("cp.async.wait_group 0;" ::: "memory");
        }
        __syncthreads();

        uint32_t sb = sbase + (uint32_t)((c & 1) * STAGE);
#pragma unroll
        for (int s = 0; s < 2; s++) {
            uint32_t af[2][2][4];
#pragma unroll
            for (int mt = 0; mt < 2; mt++) {
                ldmx4(af[mt][0], sb + SM_AH + a_off[mt] + s * 32);
                ldmx4(af[mt][1], sb + SM_AL + a_off[mt] + s * 32);
            }
#pragma unroll
            for (int p = 0; p < 8; p++) {
                uint32_t rh[4], rl[4];
                ldmx4(rh, sb + SM_BH + b_base + (uint32_t)(p * 16 * 80) + s * 32);
                ldmx4(rl, sb + SM_BL + b_base + (uint32_t)(p * 16 * 80) + s * 32);
#pragma unroll
                for (int mt = 0; mt < 2; mt++) {
                    mma16816(acc[mt][2 * p],     af[mt][0], rh);
                    mma16816(acc[mt][2 * p],     af[mt][0], rl);
                    mma16816(acc[mt][2 * p],     af[mt][1], rh);
                    mma16816(acc[mt][2 * p + 1], af[mt][0], rh + 2);
                    mma16816(acc[mt][2 * p + 1], af[mt][0], rl + 2);
                    mma16816(acc[mt][2 * p + 1], af[mt][1], rh + 2);
                }
            }
        }
        __syncthreads();
    }

#pragma unroll
    for (int mt = 0; mt < 2; mt++) {
        int m1 = m0 + warp_m + mt * 16 + (l >> 2);
        int m2 = m1 + 8;
#pragma unroll
        for (int nt = 0; nt < 16; nt++) {
            int nc = warp_n + nt * 8 + 2 * (l & 3);
            if (m1 < NN)
                *(float2*)(g_H + (size_t)m1 * 256 + nc) =
                    make_float2(acc[mt][nt][0], acc[mt][nt][1]);
            if (m2 < NN)
                *(float2*)(g_H + (size_t)m2 * 256 + nc) =
                    make_float2(acc[mt][nt][2], acc[mt][nt][3]);
        }
    }
}

// ---------------- weight transpose + bf16 split (smem-tiled) -------------------
__global__ void prep_wT(const float* __restrict__ Wroot,
                        const float* __restrict__ Wrel, int K) {
    __shared__ float sm[32][65];
    int tid = threadIdx.x;
    int k0 = blockIdx.x * 32;
    int cb = blockIdx.y;
#pragma unroll
    for (int i = 0; i < 8; i++) {
        int e = tid + i * 256;
        int k = e >> 6, h = e & 63;
        float wv = (cb == 0) ? Wroot[(size_t)(k0 + k) * 64 + h]
                             : Wrel[(size_t)(cb - 1) * K * 64 + (size_t)(k0 + k) * 64 + h];
        sm[k][h] = wv;
    }
    __syncthreads();
#pragma unroll
    for (int i = 0; i < 8; i++) {
        int e = tid + i * 256;
        int h = e >> 5, kk = e & 31;
        float wv = sm[kk][h];
        __nv_bfloat16 hi = __float2bfloat16(wv);
        float lo = wv - __bfloat162float(hi);
        size_t o = (size_t)(cb * 64 + h) * K + k0 + kk;
        g_Wth[o] = hi;
        g_Wtl[o] = __float2bfloat16(lo);
    }
}

// ---------------- graph preprocessing ------------------------------------------
__global__ void zero_kernel() {
    int i = blockIdx.x * blockDim.x + threadIdx.x;
    if (i < NN * 3) g_cnt[i] = 0;
    if (i < NN) g_deg[i] = 0;
    if (i < NCRYS * 128) g_pool[i] = 0.f;
}

__global__ void count_kernel(const int* __restrict__ nbr,
                             const int* __restrict__ species) {
    int e = blockIdx.x * blockDim.x + threadIdx.x;
    if (e >= EE) return;
    int src = e / NEIGH;
    int dst = nbr[e];
    int et = species[src] + species[dst];
    atomicAdd(&g_cnt[dst * 3 + et], 1);
    atomicAdd(&g_deg[dst], 1);
}

__global__ void scan_kernel() {
    __shared__ int ps[1024];
    int t = threadIdx.x;
    int base = t * 20;
    int local[20];
    int s = 0;
#pragma unroll
    for (int i = 0; i < 20; i++) {
        int idx = base + i;
        int d = (idx < NN) ? g_deg[idx] : 0;
        local[i] = s;
        s += d;
    }
    ps[t] = s;
    __syncthreads();
    for (int off = 1; off < 1024; off <<= 1) {
        int v = (t >= off) ? ps[t - off] : 0;
        __syncthreads();
        ps[t] += v;
        __syncthreads();
    }
    int pre = (t > 0) ? ps[t - 1] : 0;
#pragma unroll
    for (int i = 0; i < 20; i++) {
        int idx = base + i;
        if (idx < NN) {
            g_off[idx] = pre + local[i];
            g_pos[idx] = pre + local[i];
        }
    }
    if (t == 1023) g_off[NN] = ps[1023];
}

__global__ void fill_kernel(const int* __restrict__ nbr,
                            const int* __restrict__ species) {
    int e = blockIdx.x * blockDim.x + threadIdx.x;
    if (e >= EE) return;
    int src = e / NEIGH;
    int dst = nbr[e];
    int et = species[src] + species[dst];
    int p = atomicAdd(&g_pos[dst], 1);
    g_rev[p] = (src << 2) | et;
}

// ---------------- gather aggregation (fused bias + relu + output) --------------
template<int OUT>
__global__ void gather_kernel(const float* __restrict__ bias,
                              __nv_bfloat16* __restrict__ oh,
                              __nv_bfloat16* __restrict__ ol,
                              float* __restrict__ of) {
    int tid = threadIdx.x;
    int dst = blockIdx.x * 4 + (tid >> 6);
    int h = tid & 63;
    if (dst >= NN) return;
    int c0 = g_cnt[dst * 3 + 0], c1 = g_cnt[dst * 3 + 1], c2 = g_cnt[dst * 3 + 2];
    float inv0 = 1.0f / (float)(c0 > 0 ? c0 : 1);
    float inv1 = 1.0f / (float)(c1 > 0 ? c1 : 1);
    float inv2 = 1.0f / (float)(c2 > 0 ? c2 : 1);
    float v = g_H[(size_t)dst * 256 + h] + bias[h];
    int b0 = g_off[dst], b1 = g_off[dst + 1];
    for (int p = b0; p < b1; p++) {
        int pk = g_rev[p];
        int src = pk >> 2, et = pk & 3;
        float ic = (et == 0) ? inv0 : ((et == 1) ? inv1 : inv2);
        v += g_H[(size_t)src * 256 + (et + 1) * 64 + h] * ic;
    }
    v = v > 0.f ? v : 0.f;
    if (OUT == 0) {
        __nv_bfloat16 hi = __float2bfloat16(v);
        oh[dst * 64 + h] = hi;
        ol[dst * 64 + h] = __float2bfloat16(v - __bfloat162float(hi));
    } else {
        of[dst * 64 + h] = v;
    }
}

// ---------------- pooling + FC ---------------------------------------------------
#define POOL_NODES 160
__global__ void pool_kernel(const int* __restrict__ crys) {
    __shared__ int starts[NCRYS];
    int t = threadIdx.x;
    if (t < NCRYS) starts[t] = crys[t * 2];
    __syncthreads();
    int v0 = blockIdx.x * POOL_NODES;
    int v1 = v0 + POOL_NODES;
    if (v1 > NN) v1 = NN;
    const float* srcbuf = (t < 64) ? g_bf : g_af;
    int h = t & 63;
    float sum = 0.f;
    int cur = -2;
    for (int v = v0; v < v1; v++) {
        int c = 0;
#pragma unroll
        for (int k = 1; k < NCRYS; k++)
            if (starts[k] <= v) c = k;
        if (c != cur) {
            if (cur >= 0) atomicAdd(&g_pool[cur * 128 + t], sum);
            sum = 0.f;
            cur = c;
        }
        sum += srcbuf[v * 64 + h];
    }
    if (cur >= 0) atomicAdd(&g_pool[cur * 128 + t], sum);
}

__global__ void fc_kernel(const int* __restrict__ crys,
                          const float* __restrict__ W,
                          const float* __restrict__ b,
                          float* __restrict__ out) {
    int t = threadIdx.x;
    if (t >= NCRYS * 2) return;
    int c = t >> 1, o = t & 1;
    float cnt = (float)(crys[c * 2 + 1] - crys[c * 2]);
    float inv = 1.0f / cnt;
    float s = 0.f;
    for (int h = 0; h < 128; h++)
        s += g_pool[c * 128 + h] * inv * W[h * 2 + o];
    out[t] = s + b[o];
}

// ---------------- launch ----------------------------------------------------------
extern "C" void kernel_launch(void* const* d_in, const int* in_sizes, int n_in,
                              void* d_out, int out_size) {
    const float* bond     = (const float*)d_in[0];
    const float* angle    = (const float*)d_in[1];
    const int*   species  = (const int*)d_in[2];
    const int*   nbr      = (const int*)d_in[3];
    const int*   crys     = (const int*)d_in[4];
    const float* W1b_rel  = (const float*)d_in[5];
    const float* W1b_root = (const float*)d_in[6];
    const float* b1b      = (const float*)d_in[7];
    const float* W1a_rel  = (const float*)d_in[8];
    const float* W1a_root = (const float*)d_in[9];
    const float* b1a      = (const float*)d_in[10];
    const float* W2b_rel  = (const float*)d_in[11];
    const float* W2b_root = (const float*)d_in[12];
    const float* b2b      = (const float*)d_in[13];
    const float* W2a_rel  = (const float*)d_in[14];
    const float* W2a_root = (const float*)d_in[15];
    const float* b2a      = (const float*)d_in[16];
    const float* fcW      = (const float*)d_in[17];
    const float* fcb      = (const float*)d_in[18];
    float* out = (float*)d_out;

    cudaFuncSetAttribute(gemm_mma<0>, cudaFuncAttributeMaxDynamicSharedMemorySize, SMEM_GEMM);
    cudaFuncSetAttribute(gemm_mma<1>, cudaFuncAttributeMaxDynamicSharedMemorySize, SMEM_GEMM);
    cudaFuncSetAttribute(gemm_mma<2>, cudaFuncAttributeMaxDynamicSharedMemorySize, SMEM_GEMM);

    __nv_bfloat16 *Wth, *Wtl, *bfh, *bfl, *afh, *afl;
    float *bfp, *afp;
    cudaGetSymbolAddress((void**)&Wth, g_Wth);
    cudaGetSymbolAddress((void**)&Wtl, g_Wtl);
    cudaGetSymbolAddress((void**)&bfh, g_bfh);
    cudaGetSymbolAddress((void**)&bfl, g_bfl);
    cudaGetSymbolAddress((void**)&afh, g_afh);
    cudaGetSymbolAddress((void**)&afl, g_afl);
    cudaGetSymbolAddress((void**)&bfp, g_bf);
    cudaGetSymbolAddress((void**)&afp, g_af);

    const int T = 256;
    const int GBLK = (NN + 127) / 128;   // 157
    const int GGRID = (NN + 3) / 4;

    // graph preprocessing (once, reused by all 4 layers)
    zero_kernel<<<(NN * 3 + T - 1) / T, T>>>();
    count_kernel<<<(EE + T - 1) / T, T>>>(nbr, species);
    scan_kernel<<<1, 1024>>>();
    fill_kernel<<<(EE + T - 1) / T, T>>>(nbr, species);

    // --- bond, layer 1 (fused expansion)
    prep_wT<<<dim3(INB / 32, 4), 256>>>(W1b_root, W1b_rel, INB);
    gemm_mma<1><<<GBLK, 256, SMEM_GEMM>>>(bond, nullptr, Wth, Wtl, INB);
    gather_kernel<0><<<GGRID, 256>>>(b1b, bfh, bfl, nullptr);

    // --- angle, layer 1 (fused expansion)
    prep_wT<<<dim3(INA / 32, 4), 256>>>(W1a_root, W1a_rel, INA);
    gemm_mma<2><<<GBLK, 256, SMEM_GEMM>>>(angle, nullptr, Wth, Wtl, INA);
    gather_kernel<0><<<GGRID, 256>>>(b1a, afh, afl, nullptr);

    // --- bond, layer 2
    prep_wT<<<dim3(HD / 32, 4), 256>>>(W2b_root, W2b_rel, HD);
    gemm_mma<0><<<GBLK, 256, SMEM_GEMM>>>(bfh, bfl, Wth, Wtl, HD);
    gather_kernel<1><<<GGRID, 256>>>(b2b, nullptr, nullptr, bfp);

    // --- angle, layer 2
    prep_wT<<<dim3(HD / 32, 4), 256>>>(W2a_root, W2a_rel, HD);
    gemm_mma<0><<<GBLK, 256, SMEM_GEMM>>>(afh, afl, Wth, Wtl, HD);
    gather_kernel<1><<<GGRID, 256>>>(b2a, nullptr, nullptr, afp);

    // --- pooling + FC
    pool_kernel<<<(NN + POOL_NODES - 1) / POOL_NODES, 128>>>(crys);
    fc_kernel<<<1, 64>>>(crys, fcW, fcb, out);
}